// round 2
// baseline (speedup 1.0000x reference)
#include <cuda_runtime.h>

// QuantizedTopKSparsity == out[r,c] = rint( x[r,c] / (max_c |x[r,c]| + 1e-6) )
// (quantized values are in {-1,0,+1}; the top-k mask is an identity on x_q).
//
// Persistent, software-pipelined version:
//  - grid = 148 SMs * 4 CTAs (one wave, no wave-transition DRAM bubbles)
//  - each CTA strides over rows; while reducing/storing row r it has already
//    issued the loads for row r+stride (double-buffered registers), so the
//    LSU always has LDG.128s in flight.
//  - parity double-buffered smem absmax slots -> one __syncthreads per row.

#define ROW_LEN 4096
#define THREADS 256
#define V4 4              // 4 float4 = 16 floats per thread; 256*16 = 4096
#define CTAS_PER_SM 4
#define NUM_SMS 148

__device__ __forceinline__ float absmax4(const float4& a) {
    return fmaxf(fmaxf(fabsf(a.x), fabsf(a.y)), fmaxf(fabsf(a.z), fabsf(a.w)));
}

__global__ __launch_bounds__(THREADS, CTAS_PER_SM)
void qtopk_kernel(const float* __restrict__ x, float* __restrict__ out, int rows) {
    const int t = threadIdx.x;
    const int stride = gridDim.x;
    int row = blockIdx.x;
    if (row >= rows) return;

    __shared__ float smax[2][THREADS / 32];

    float4 cur[V4], nxt[V4];

    // Prologue: load first row into cur.
    {
        const float4* __restrict__ xr =
            reinterpret_cast<const float4*>(x + (size_t)row * ROW_LEN);
#pragma unroll
        for (int i = 0; i < V4; i++) cur[i] = xr[t + i * THREADS];
    }

    int par = 0;
    for (; row < rows; row += stride, par ^= 1) {
        const int nrow = row + stride;

        // Issue next row's loads early — latency hidden behind reduce + store.
        if (nrow < rows) {
            const float4* __restrict__ xr =
                reinterpret_cast<const float4*>(x + (size_t)nrow * ROW_LEN);
#pragma unroll
            for (int i = 0; i < V4; i++) nxt[i] = xr[t + i * THREADS];
        }

        // Block absmax of cur.
        float m = 0.0f;
#pragma unroll
        for (int i = 0; i < V4; i++) m = fmaxf(m, absmax4(cur[i]));
#pragma unroll
        for (int o = 16; o > 0; o >>= 1)
            m = fmaxf(m, __shfl_xor_sync(0xffffffffu, m, o));
        if ((t & 31) == 0) smax[par][t >> 5] = m;
        __syncthreads();

        float g = smax[par][0];
#pragma unroll
        for (int w = 1; w < THREADS / 32; w++) g = fmaxf(g, smax[par][w]);
        const float inv = 1.0f / (g + 1e-6f);

        // Quantize + store from registers.
        float4* __restrict__ orow =
            reinterpret_cast<float4*>(out + (size_t)row * ROW_LEN);
#pragma unroll
        for (int i = 0; i < V4; i++) {
            float4 o;
            o.x = rintf(cur[i].x * inv);
            o.y = rintf(cur[i].y * inv);
            o.z = rintf(cur[i].z * inv);
            o.w = rintf(cur[i].w * inv);
            orow[t + i * THREADS] = o;
        }

        // Rotate buffers (consumes nxt — first point that waits on its loads).
        if (nrow < rows) {
#pragma unroll
            for (int i = 0; i < V4; i++) cur[i] = nxt[i];
        }
    }
}

extern "C" void kernel_launch(void* const* d_in, const int* in_sizes, int n_in,
                              void* d_out, int out_size) {
    const float* x = (const float*)d_in[0];
    float* out = (float*)d_out;
    const int rows = in_sizes[0] / ROW_LEN;     // 8192
    int grid = NUM_SMS * CTAS_PER_SM;           // 592 — one resident wave
    if (grid > rows) grid = rows;
    qtopk_kernel<<<grid, THREADS>>>(x, out, rows);
}

// round 3
// speedup vs baseline: 1.1000x; 1.1000x over previous
#include <cuda_runtime.h>

// QuantizedTopKSparsity == out[r,c] = rint( x[r,c] / (max_c |x[r,c]| + 1e-6) )
// (quantized values are in {-1,0,+1}; the top-k mask is an identity on x_q).
//
// Round-3: back to the simple one-CTA-per-row form (measured equal-best, higher
// occupancy, better wall time than persistent), plus streaming cache hints on
// both the load and store streams (__ldcs/__stcs) to reduce L2 pollution and
// DRAM read/write turnaround on this touch-once 1:1 streaming pattern.

#define ROW_LEN 4096
#define THREADS 256
#define V4 4   // 4 float4 = 16 floats per thread; 256*16 = 4096

__global__ __launch_bounds__(THREADS)
void qtopk_kernel(const float* __restrict__ x, float* __restrict__ out, int rows) {
    const int row = blockIdx.x;
    if (row >= rows) return;

    const float4* __restrict__ xr =
        reinterpret_cast<const float4*>(x + (size_t)row * ROW_LEN);
    float4* __restrict__ orow =
        reinterpret_cast<float4*>(out + (size_t)row * ROW_LEN);

    const int t = threadIdx.x;

    // Streaming loads (evict-first), coalesced stripes; accumulate absmax.
    float4 v[V4];
    float m = 0.0f;
#pragma unroll
    for (int i = 0; i < V4; i++) {
        v[i] = __ldcs(&xr[t + i * THREADS]);
        m = fmaxf(m, fmaxf(fmaxf(fabsf(v[i].x), fabsf(v[i].y)),
                           fmaxf(fabsf(v[i].z), fabsf(v[i].w))));
    }

    // Warp absmax
#pragma unroll
    for (int o = 16; o > 0; o >>= 1)
        m = fmaxf(m, __shfl_xor_sync(0xffffffffu, m, o));

    // Cross-warp absmax via smem (8 warps)
    __shared__ float smax[THREADS / 32];
    if ((t & 31) == 0) smax[t >> 5] = m;
    __syncthreads();

    float g = smax[0];
#pragma unroll
    for (int w = 1; w < THREADS / 32; w++) g = fmaxf(g, smax[w]);

    const float inv = 1.0f / (g + 1e-6f);

    // Quantize from registers and store with streaming hint.
#pragma unroll
    for (int i = 0; i < V4; i++) {
        float4 o;
        o.x = rintf(v[i].x * inv);
        o.y = rintf(v[i].y * inv);
        o.z = rintf(v[i].z * inv);
        o.w = rintf(v[i].w * inv);
        __stcs(&orow[t + i * THREADS], o);
    }
}

extern "C" void kernel_launch(void* const* d_in, const int* in_sizes, int n_in,
                              void* d_out, int out_size) {
    const float* x = (const float*)d_in[0];
    float* out = (float*)d_out;
    const int rows = in_sizes[0] / ROW_LEN;   // 8192
    qtopk_kernel<<<rows, THREADS>>>(x, out, rows);
}